// round 3
// baseline (speedup 1.0000x reference)
#include <cuda_runtime.h>
#include <cuda_fp16.h>
#include <math.h>

#define GD     17
#define NS     4096
#define DD     768
#define NHH    30
#define CHH    31
#define NCELL  4913      /* 17^3 */
#define NCHUNK 64
#define CHUNK  64
#define K4_CG  296
#define K4_GRID (K4_CG*2)
#define HH     15        /* h per group */
#define MAXCAND 768

/* ---------------- scratch (static device globals: allocation-free) ------- */
__device__ __align__(16) float  g_w[NS][12];
__device__              int    g_cells[NS][3];
__device__              float  g_dist[NS];
__device__              int    g_bin[NS];
__device__              int    g_binCount[NCELL];
__device__              int    g_binStart[NCELL + 1];
__device__              int    g_binCursor[NCELL];
__device__              int    g_binSamples[NS];
__device__ __align__(16) __half g_Ed[NCELL * DD];      /* fp16 density slice */
__device__ __align__(16) float  g_sd[NS * DD];          /* fp32: scan precision */
__device__ __align__(16) __half g_wgt[NS * DD];         /* fp16 weights */
__device__ __align__(16) float  g_S[NCHUNK * DD];
__device__ __align__(16) float  g_A[NCELL * DD];
__device__ __align__(16) float  g_part[K4_GRID * HH * DD];

/* ---------------- K-init: clear bin counts + fp16-convert density -------- */
__global__ void k_init(const float* __restrict__ E) {
    int i = blockIdx.x * blockDim.x + threadIdx.x;
    if (i < NCELL) g_binCount[i] = 0;
    if (i < NCELL * DD) {
        int cell = i / DD;
        int d    = i - cell * DD;
        g_Ed[i] = __float2half(E[cell * (CHH*DD) + NHH*DD + d]);
    }
}

/* ---------------- K0: per-sample prep (weights, cells, dist, bin) -------- */
__global__ void k_prep(const float* __restrict__ samples,
                       const float* __restrict__ lastp) {
    int n = blockIdx.x * blockDim.x + threadIdx.x;
    if (n >= NS) return;

    float s[3] = { samples[3*n], samples[3*n+1], samples[3*n+2] };
    float nx[3];
    if (n < NS - 1) { nx[0]=samples[3*n+3]; nx[1]=samples[3*n+4]; nx[2]=samples[3*n+5]; }
    else            { nx[0]=lastp[0];       nx[1]=lastp[1];       nx[2]=lastp[2]; }
    float e0=s[0]-nx[0], e1=s[1]-nx[1], e2=s[2]-nx[2];
    g_dist[n] = sqrtf(e0*e0 + e1*e1 + e2*e2);

    int fi[3];
    #pragma unroll
    for (int a = 0; a < 3; a++) {
        float p  = s[a] + 8.0f;
        float f  = floorf(p);
        int  fii = (int)f;
        float dd = p - f;
        int  q   = (a == 0) ? (fii + 1) : (int)ceilf(p);   /* x uses f+1; y,z use ceil */
        int c0 = fii;
        int c1 = min(q, GD - 1);
        int c2 = max(fii - 1, 0);
        int c3 = min(q + 1, GD - 1);
        float mlo = (fii > 0)      ? 1.0f : 0.0f;
        float mhi = (fii + 2 < GD) ? 1.0f : 0.0f;
        float inv = 1.0f / (2.0f + mlo + mhi);
        g_w[n][a*4+0] = (2.0f - dd) * inv;
        g_w[n][a*4+1] = (1.0f + dd) * inv;
        g_w[n][a*4+2] = (1.0f - dd) * mlo * inv;
        g_w[n][a*4+3] = dd * mhi * inv;
        g_cells[n][a] = c0 | (c1 << 8) | (c2 << 16) | (c3 << 24);
        fi[a] = fii;
    }
    int bin = (fi[0]*GD + fi[1])*GD + fi[2];
    g_bin[n] = bin;
    atomicAdd(&g_binCount[bin], 1);
}

/* ---------------- K-build: warp-shuffle scan + scatter + sort ------------ */
__global__ void k_build() {
    int t = threadIdx.x;                   /* 1024 threads */
    /* phase 1: each thread owns 5 contiguous cells */
    int vals[5]; int s = 0;
    #pragma unroll
    for (int k = 0; k < 5; k++) {
        int idx = t*5 + k;
        int v = (idx < NCELL) ? g_binCount[idx] : 0;
        vals[k] = v; s += v;
    }
    int lane = t & 31, wid = t >> 5;
    int inc = s;
    #pragma unroll
    for (int off = 1; off < 32; off <<= 1) {
        int x = __shfl_up_sync(0xffffffffu, inc, off);
        if (lane >= off) inc += x;
    }
    __shared__ int wsum[32];
    if (lane == 31) wsum[wid] = inc;
    __syncthreads();
    if (wid == 0) {
        int v = wsum[lane];
        #pragma unroll
        for (int off = 1; off < 32; off <<= 1) {
            int x = __shfl_up_sync(0xffffffffu, v, off);
            if (lane >= off) v += x;
        }
        wsum[lane] = v;
    }
    __syncthreads();
    int base = inc - s + ((wid > 0) ? wsum[wid-1] : 0);
    #pragma unroll
    for (int k = 0; k < 5; k++) {
        int idx = t*5 + k;
        if (idx < NCELL) {
            g_binStart[idx]  = base;
            g_binCursor[idx] = base;
            base += vals[k];
        }
    }
    if (t == 0) g_binStart[NCELL] = NS;
    __syncthreads();
    /* phase 2: scatter sample ids */
    for (int n = t; n < NS; n += 1024) {
        int pos = atomicAdd(&g_binCursor[g_bin[n]], 1);
        g_binSamples[pos] = n;
    }
    __syncthreads();
    /* phase 3: insertion-sort each bin for determinism */
    for (int b = t; b < NCELL; b += 1024) {
        int s0 = g_binStart[b], s1 = g_binStart[b + 1];
        for (int i = s0 + 1; i < s1; i++) {
            int v = g_binSamples[i];
            int j = i - 1;
            while (j >= s0 && g_binSamples[j] > v) { g_binSamples[j+1] = g_binSamples[j]; j--; }
            g_binSamples[j + 1] = v;
        }
    }
}

/* ---------------- K1: density interp (fp16 table, 8d/thread) ------------- */
__global__ void __launch_bounds__(192) k_density() {
    __shared__ float2 sco[2][64];          /* (coef, offset-as-int) */
    __shared__ float  sw[2][12];
    __shared__ int    sc[2][3];
    int t = threadIdx.x;
    int g = (t >= 96) ? 1 : 0;
    int tl = t - g*96;
    int n = blockIdx.x*2 + g;
    if (tl < 12) sw[g][tl] = g_w[n][tl];
    if (tl < 3)  sc[g][tl] = g_cells[n][tl];
    __syncthreads();
    if (tl < 64) {
        int i = tl >> 4, j = (tl >> 2) & 3, k = tl & 3;
        int cx = (sc[g][0] >> (8*i)) & 255;
        int cy = (sc[g][1] >> (8*j)) & 255;
        int cz = (sc[g][2] >> (8*k)) & 255;
        float c = sw[g][i] * sw[g][4 + j] * sw[g][8 + k];
        int off = ((cx*GD + cy)*GD + cz) * DD;
        sco[g][tl] = make_float2(c, __int_as_float(off));
    }
    __syncthreads();
    int d8 = tl * 8;
    const __half* Ep = g_Ed + d8;
    float a0=0.f,a1=0.f,a2=0.f,a3=0.f,a4=0.f,a5=0.f,a6=0.f,a7=0.f;
    #pragma unroll 4
    for (int m = 0; m < 64; m++) {
        float2 co = sco[g][m];
        float c = co.x;
        if (c != 0.0f) {
            uint4 u = *reinterpret_cast<const uint4*>(Ep + __float_as_int(co.y));
            float2 f0 = __half22float2(*reinterpret_cast<const __half2*>(&u.x));
            float2 f1 = __half22float2(*reinterpret_cast<const __half2*>(&u.y));
            float2 f2 = __half22float2(*reinterpret_cast<const __half2*>(&u.z));
            float2 f3 = __half22float2(*reinterpret_cast<const __half2*>(&u.w));
            a0 += c*f0.x; a1 += c*f0.y; a2 += c*f1.x; a3 += c*f1.y;
            a4 += c*f2.x; a5 += c*f2.y; a6 += c*f3.x; a7 += c*f3.y;
        }
    }
    float dist = g_dist[n];
    float4 o0, o1;
    o0.x = fmaxf(a0,0.f)*dist; o0.y = fmaxf(a1,0.f)*dist;
    o0.z = fmaxf(a2,0.f)*dist; o0.w = fmaxf(a3,0.f)*dist;
    o1.x = fmaxf(a4,0.f)*dist; o1.y = fmaxf(a5,0.f)*dist;
    o1.z = fmaxf(a6,0.f)*dist; o1.w = fmaxf(a7,0.f)*dist;
    *reinterpret_cast<float4*>(g_sd + n*DD + d8)     = o0;
    *reinterpret_cast<float4*>(g_sd + n*DD + d8 + 4) = o1;
}

/* ---------------- K2a: chunk partial sums of sd --------------------------- */
__global__ void k_chunksum() {
    int idx = blockIdx.x * blockDim.x + threadIdx.x;   /* NCHUNK*DD threads */
    int chunk = idx / DD;
    int d = idx - chunk * DD;
    int base = chunk * CHUNK * DD + d;
    float s = 0.f;
    #pragma unroll 8
    for (int i = 0; i < CHUNK; i++) s += g_sd[base + i*DD];
    g_S[chunk*DD + d] = s;
}

/* ---------------- K2b: exclusive scan + weights (fp16 out) ---------------- */
__global__ void k_wgt() {
    int idx = blockIdx.x * blockDim.x + threadIdx.x;
    int chunk = idx / DD;
    int d = idx - chunk * DD;
    float excl = 0.f;
    for (int j = 0; j < chunk; j++) excl += g_S[j*DD + d];
    int base = chunk * CHUNK * DD + d;
    for (int i = 0; i < CHUNK; i++) {
        float sd = g_sd[base + i*DD];
        float T = __expf(-excl);
        float alpha = 1.0f - __expf(-sd);
        g_wgt[base + i*DD] = __float2half(T * alpha);
        excl += sd;
    }
}

/* ---------------- K3: A[c,d] gather (96 thr/cell, 8d/thread) -------------- */
__global__ void __launch_bounds__(96) k_A() {
    __shared__ int    slist[MAXCAND];
    __shared__ float2 scand[MAXCAND];      /* (coef, byteoff-as-int) */
    __shared__ int   scnt[64];
    __shared__ int   soff2[64];
    __shared__ int   sstart[64];
    __shared__ int   s_tot;
    int c = blockIdx.x;
    int iz = c % GD; int r = c / GD; int iy = r % GD; int ix = r / GD;
    int x0 = max(ix-2,0), x1 = min(ix+1,GD-1);
    int y0 = max(iy-2,0), y1 = min(iy+1,GD-1);
    int z0 = max(iz-2,0), z1 = min(iz+1,GD-1);
    int nxb = x1-x0+1, nyb = y1-y0+1, nzb = z1-z0+1;
    int nb = nxb * nyb * nzb;
    int t = threadIdx.x;

    if (t < nb) {
        int bi = t / (nyb*nzb); int rr = t - bi*(nyb*nzb);
        int bj = rr / nzb;      int bk = rr - bj*nzb;
        int b = ((x0+bi)*GD + (y0+bj))*GD + (z0+bk);
        sstart[t] = g_binStart[b];
        scnt[t]   = g_binStart[b+1] - g_binStart[b];
    }
    __syncthreads();
    if (t == 0) {
        int acc = 0;
        for (int i = 0; i < nb; i++) { soff2[i] = acc; acc += scnt[i]; }
        s_tot = (acc < MAXCAND) ? acc : MAXCAND;
    }
    __syncthreads();
    int tot = s_tot;
    if (t < nb) {
        int off = soff2[t], st = sstart[t], cn = scnt[t];
        for (int k = 0; k < cn; k++)
            if (off + k < MAXCAND) slist[off + k] = g_binSamples[st + k];
    }
    __syncthreads();
    /* coefficients: one candidate per thread */
    for (int i = t; i < tot; i += 96) {
        int n = slist[i];
        int cpx = g_cells[n][0], cpy = g_cells[n][1], cpz = g_cells[n][2];
        float wx = 0.f, wy = 0.f, wz = 0.f;
        #pragma unroll
        for (int u = 0; u < 4; u++) {
            if (((cpx >> (8*u)) & 255) == ix) wx += g_w[n][u];
            if (((cpy >> (8*u)) & 255) == iy) wy += g_w[n][4 + u];
            if (((cpz >> (8*u)) & 255) == iz) wz += g_w[n][8 + u];
        }
        scand[i] = make_float2(wx * wy * wz, __int_as_float(n * DD));
    }
    __syncthreads();
    int d8 = t * 8;
    const __half* Wp = g_wgt + d8;
    float a0=0.f,a1=0.f,a2=0.f,a3=0.f,a4=0.f,a5=0.f,a6=0.f,a7=0.f;
    for (int i = 0; i < tot; i++) {
        float2 ca = scand[i];
        float cf = ca.x;
        if (cf != 0.0f) {
            uint4 u = *reinterpret_cast<const uint4*>(Wp + __float_as_int(ca.y));
            float2 f0 = __half22float2(*reinterpret_cast<const __half2*>(&u.x));
            float2 f1 = __half22float2(*reinterpret_cast<const __half2*>(&u.y));
            float2 f2 = __half22float2(*reinterpret_cast<const __half2*>(&u.z));
            float2 f3 = __half22float2(*reinterpret_cast<const __half2*>(&u.w));
            a0 += cf*f0.x; a1 += cf*f0.y; a2 += cf*f1.x; a3 += cf*f1.y;
            a4 += cf*f2.x; a5 += cf*f2.y; a6 += cf*f3.x; a7 += cf*f3.y;
        }
    }
    float4 o0, o1;
    o0.x=a0; o0.y=a1; o0.z=a2; o0.w=a3;
    o1.x=a4; o1.y=a5; o1.z=a6; o1.w=a7;
    *reinterpret_cast<float4*>(g_A + c*DD + d8)     = o0;
    *reinterpret_cast<float4*>(g_A + c*DD + d8 + 4) = o1;
}

/* ---------------- K4: out partials = sum_c A[c,d]*E[c,h,d] ---------------- */
__global__ void __launch_bounds__(192, 2) k_out(const float* __restrict__ E) {
    int cg = blockIdx.x >> 1;
    int hg = blockIdx.x & 1;
    int t = threadIdx.x;
    int d4 = t * 4;
    float4 acc[HH];
    #pragma unroll
    for (int h = 0; h < HH; h++) { acc[h].x=0.f; acc[h].y=0.f; acc[h].z=0.f; acc[h].w=0.f; }

    for (int c = cg; c < NCELL; c += K4_CG) {
        float4 a = *reinterpret_cast<const float4*>(g_A + c*DD + d4);
        if (a.x == 0.f && a.y == 0.f && a.z == 0.f && a.w == 0.f) continue;
        const float4* base = reinterpret_cast<const float4*>(E + c*(CHH*DD) + hg*HH*DD + d4);
        #pragma unroll
        for (int h = 0; h < HH; h++) {
            float4 e = __ldcs(base + h*(DD/4));
            acc[h].x += a.x * e.x;
            acc[h].y += a.y * e.y;
            acc[h].z += a.z * e.z;
            acc[h].w += a.w * e.w;
        }
    }
    float* pb = g_part + blockIdx.x * (HH*DD);
    #pragma unroll
    for (int h = 0; h < HH; h++)
        *reinterpret_cast<float4*>(pb + h*DD + d4) = acc[h];
}

/* ---------------- K5: reduce partials -> d_out ---------------------------- */
__global__ void k_reduce(float* __restrict__ out) {
    int idx = blockIdx.x * blockDim.x + threadIdx.x;   /* 5760 threads */
    if (idx >= (NHH * DD) / 4) return;
    int h  = idx / (DD/4);
    int d4 = (idx - h*(DD/4)) * 4;
    int g  = h / HH;
    int hh = h - g*HH;
    float ax=0.f, ay=0.f, az=0.f, aw=0.f;
    #pragma unroll 4
    for (int cg = 0; cg < K4_CG; cg++) {
        const float4 v = *reinterpret_cast<const float4*>(
            g_part + (cg*2 + g) * (HH*DD) + hh*DD + d4);
        ax += v.x; ay += v.y; az += v.z; aw += v.w;
    }
    float4 o; o.x=ax; o.y=ay; o.z=az; o.w=aw;
    *reinterpret_cast<float4*>(out + h*DD + d4) = o;
}

/* ---------------- launcher ------------------------------------------------ */
extern "C" void kernel_launch(void* const* d_in, const int* in_sizes, int n_in,
                              void* d_out, int out_size) {
    const float* samples = (const float*)d_in[0];
    const float* lastp   = (const float*)d_in[1];
    const float* E       = (const float*)d_in[2];
    for (int i = 0; i < n_in; i++) {
        if (in_sizes[i] == NS * 3)            samples = (const float*)d_in[i];
        else if (in_sizes[i] == 3)            lastp   = (const float*)d_in[i];
        else if (in_sizes[i] > 1000000)       E       = (const float*)d_in[i];
    }

    k_init    <<<(NCELL*DD + 255)/256, 256>>>(E);
    k_prep    <<<(NS + 255)/256, 256>>>(samples, lastp);
    k_build   <<<1, 1024>>>();
    k_density <<<NS/2, 192>>>();
    k_chunksum<<<(NCHUNK*DD)/256, 256>>>();
    k_wgt     <<<(NCHUNK*DD)/256, 256>>>();
    k_A       <<<NCELL, 96>>>();
    k_out     <<<K4_GRID, 192>>>(E);
    k_reduce  <<<30, 192>>>((float*)d_out);
    (void)out_size;
}

// round 4
// speedup vs baseline: 1.0703x; 1.0703x over previous
#include <cuda_runtime.h>
#include <cuda_fp16.h>
#include <math.h>

#define GD     17
#define NS     4096
#define DD     768
#define NHH    30
#define CHH    31
#define NCELL  4913      /* 17^3 */
#define NCHUNK 64
#define CHUNK  64
#define K4_CG  296
#define K4_GRID (K4_CG*2)
#define HH     15        /* h per group */
#define MAXCAND 1536

/* ---------------- scratch (static device globals: allocation-free) ------- */
__device__ __align__(16) float  g_w[NS][12];
__device__              int    g_cells[NS][3];
__device__              float  g_dist[NS];
__device__              int    g_bin[NS];
__device__              int    g_binCount[NCELL];
__device__              int    g_binStart[NCELL + 1];
__device__              int    g_binCursor[NCELL];
__device__              int    g_binSamples[NS];
__device__ __align__(16) __half g_Ed[NCELL * DD];      /* fp16 density slice */
__device__ __align__(16) float  g_sd[NS * DD];          /* fp32: scan precision */
__device__ __align__(16) __half g_wgt[NS * DD];         /* fp16 weights */
__device__ __align__(16) float  g_S[NCHUNK * DD];
__device__ __align__(16) float  g_A[NCELL * DD];
__device__ __align__(16) float  g_part[K4_GRID * HH * DD];

/* ---------------- K-init: clear bin counts + fp16-convert density -------- */
__global__ void k_init(const float* __restrict__ E) {
    int i = blockIdx.x * blockDim.x + threadIdx.x;
    if (i < NCELL) g_binCount[i] = 0;
    if (i < NCELL * DD) {
        int cell = i / DD;
        int d    = i - cell * DD;
        g_Ed[i] = __float2half(E[cell * (CHH*DD) + NHH*DD + d]);
    }
}

/* ---------------- K0: per-sample prep (weights, cells, dist, bin) -------- */
__global__ void k_prep(const float* __restrict__ samples,
                       const float* __restrict__ lastp) {
    int n = blockIdx.x * blockDim.x + threadIdx.x;
    if (n >= NS) return;

    float s[3] = { samples[3*n], samples[3*n+1], samples[3*n+2] };
    float nx[3];
    if (n < NS - 1) { nx[0]=samples[3*n+3]; nx[1]=samples[3*n+4]; nx[2]=samples[3*n+5]; }
    else            { nx[0]=lastp[0];       nx[1]=lastp[1];       nx[2]=lastp[2]; }
    float e0=s[0]-nx[0], e1=s[1]-nx[1], e2=s[2]-nx[2];
    g_dist[n] = sqrtf(e0*e0 + e1*e1 + e2*e2);

    int fi[3];
    #pragma unroll
    for (int a = 0; a < 3; a++) {
        float p  = s[a] + 8.0f;
        float f  = floorf(p);
        int  fii = (int)f;
        float dd = p - f;
        int  q   = (a == 0) ? (fii + 1) : (int)ceilf(p);   /* x uses f+1; y,z use ceil */
        int c0 = fii;
        int c1 = min(q, GD - 1);
        int c2 = max(fii - 1, 0);
        int c3 = min(q + 1, GD - 1);
        float mlo = (fii > 0)      ? 1.0f : 0.0f;
        float mhi = (fii + 2 < GD) ? 1.0f : 0.0f;
        float inv = 1.0f / (2.0f + mlo + mhi);
        g_w[n][a*4+0] = (2.0f - dd) * inv;
        g_w[n][a*4+1] = (1.0f + dd) * inv;
        g_w[n][a*4+2] = (1.0f - dd) * mlo * inv;
        g_w[n][a*4+3] = dd * mhi * inv;
        g_cells[n][a] = c0 | (c1 << 8) | (c2 << 16) | (c3 << 24);
        fi[a] = fii;
    }
    int bin = (fi[0]*GD + fi[1])*GD + fi[2];
    g_bin[n] = bin;
    atomicAdd(&g_binCount[bin], 1);
}

/* ---------------- K-build: warp-shuffle scan + scatter + sort ------------ */
__global__ void k_build() {
    int t = threadIdx.x;                   /* 1024 threads */
    int vals[5]; int s = 0;
    #pragma unroll
    for (int k = 0; k < 5; k++) {
        int idx = t*5 + k;
        int v = (idx < NCELL) ? g_binCount[idx] : 0;
        vals[k] = v; s += v;
    }
    int lane = t & 31, wid = t >> 5;
    int inc = s;
    #pragma unroll
    for (int off = 1; off < 32; off <<= 1) {
        int x = __shfl_up_sync(0xffffffffu, inc, off);
        if (lane >= off) inc += x;
    }
    __shared__ int wsum[32];
    if (lane == 31) wsum[wid] = inc;
    __syncthreads();
    if (wid == 0) {
        int v = wsum[lane];
        #pragma unroll
        for (int off = 1; off < 32; off <<= 1) {
            int x = __shfl_up_sync(0xffffffffu, v, off);
            if (lane >= off) v += x;
        }
        wsum[lane] = v;
    }
    __syncthreads();
    int base = inc - s + ((wid > 0) ? wsum[wid-1] : 0);
    #pragma unroll
    for (int k = 0; k < 5; k++) {
        int idx = t*5 + k;
        if (idx < NCELL) {
            g_binStart[idx]  = base;
            g_binCursor[idx] = base;
            base += vals[k];
        }
    }
    if (t == 0) g_binStart[NCELL] = NS;
    __syncthreads();
    for (int n = t; n < NS; n += 1024) {
        int pos = atomicAdd(&g_binCursor[g_bin[n]], 1);
        g_binSamples[pos] = n;
    }
    __syncthreads();
    for (int b = t; b < NCELL; b += 1024) {
        int s0 = g_binStart[b], s1 = g_binStart[b + 1];
        for (int i = s0 + 1; i < s1; i++) {
            int v = g_binSamples[i];
            int j = i - 1;
            while (j >= s0 && g_binSamples[j] > v) { g_binSamples[j+1] = g_binSamples[j]; j--; }
            g_binSamples[j + 1] = v;
        }
    }
}

/* ---------------- K1: density interp (fp16 table, 4d/thread) ------------- */
__global__ void __launch_bounds__(192) k_density() {
    __shared__ float2 sco[64];             /* (coef, offset-as-int) */
    __shared__ float  sw[12];
    __shared__ int    sc[3];
    int n = blockIdx.x;
    int t = threadIdx.x;
    if (t < 12) sw[t] = g_w[n][t];
    if (t < 3)  sc[t] = g_cells[n][t];
    __syncthreads();
    if (t < 64) {
        int i = t >> 4, j = (t >> 2) & 3, k = t & 3;
        int cx = (sc[0] >> (8*i)) & 255;
        int cy = (sc[1] >> (8*j)) & 255;
        int cz = (sc[2] >> (8*k)) & 255;
        float c = sw[i] * sw[4 + j] * sw[8 + k];
        int off = ((cx*GD + cy)*GD + cz) * DD;
        sco[t] = make_float2(c, __int_as_float(off));
    }
    __syncthreads();
    int d4 = t * 4;
    const __half* Ep = g_Ed + d4;
    float ax = 0.f, ay = 0.f, az = 0.f, aw = 0.f;
    #pragma unroll 4
    for (int m = 0; m < 64; m++) {
        float2 co = sco[m];
        float c = co.x;
        uint2 u = *reinterpret_cast<const uint2*>(Ep + __float_as_int(co.y));
        float2 f0 = __half22float2(*reinterpret_cast<const __half2*>(&u.x));
        float2 f1 = __half22float2(*reinterpret_cast<const __half2*>(&u.y));
        ax += c * f0.x; ay += c * f0.y; az += c * f1.x; aw += c * f1.y;
    }
    float dist = g_dist[n];
    float4 o;
    o.x = fmaxf(ax, 0.f) * dist;
    o.y = fmaxf(ay, 0.f) * dist;
    o.z = fmaxf(az, 0.f) * dist;
    o.w = fmaxf(aw, 0.f) * dist;
    *reinterpret_cast<float4*>(g_sd + n*DD + d4) = o;
}

/* ---------------- K2a: chunk partial sums of sd --------------------------- */
__global__ void k_chunksum() {
    int idx = blockIdx.x * blockDim.x + threadIdx.x;   /* NCHUNK*DD threads */
    int chunk = idx / DD;
    int d = idx - chunk * DD;
    int base = chunk * CHUNK * DD + d;
    float s = 0.f;
    #pragma unroll 8
    for (int i = 0; i < CHUNK; i++) s += g_sd[base + i*DD];
    g_S[chunk*DD + d] = s;
}

/* ---------------- K2b: scan + weights — ONE exp per element --------------- */
__global__ void k_wgt() {
    int idx = blockIdx.x * blockDim.x + threadIdx.x;
    int chunk = idx / DD;
    int d = idx - chunk * DD;
    float excl = 0.f;
    for (int j = 0; j < chunk; j++) excl += g_S[j*DD + d];
    float T = __expf(-excl);                 /* one exp to seed the chunk */
    int base = chunk * CHUNK * DD + d;
    for (int i = 0; i < CHUNK; i++) {
        float sd = g_sd[base + i*DD];
        float e  = __expf(-sd);              /* exp(-sd): alpha AND T-update */
        g_wgt[base + i*DD] = __float2half(T * (1.0f - e));
        T *= e;
    }
}

/* ---------------- K3: A[c,d] gather (cell-centric, fp16 wgt) -------------- */
__global__ void __launch_bounds__(192) k_A() {
    __shared__ int    slist[MAXCAND];
    __shared__ float2 scand[MAXCAND];      /* (coef, offset-as-int) */
    __shared__ int   scnt[64];
    __shared__ int   soff2[64];
    __shared__ int   sstart[64];
    __shared__ int   s_tot;
    int c = blockIdx.x;
    int iz = c % GD; int r = c / GD; int iy = r % GD; int ix = r / GD;
    int x0 = max(ix-2,0), x1 = min(ix+1,GD-1);
    int y0 = max(iy-2,0), y1 = min(iy+1,GD-1);
    int z0 = max(iz-2,0), z1 = min(iz+1,GD-1);
    int nxb = x1-x0+1, nyb = y1-y0+1, nzb = z1-z0+1;
    int nb = nxb * nyb * nzb;
    int t = threadIdx.x;

    if (t < nb) {
        int bi = t / (nyb*nzb); int rr = t - bi*(nyb*nzb);
        int bj = rr / nzb;      int bk = rr - bj*nzb;
        int b = ((x0+bi)*GD + (y0+bj))*GD + (z0+bk);
        sstart[t] = g_binStart[b];
        scnt[t]   = g_binStart[b+1] - g_binStart[b];
    }
    __syncthreads();
    if (t == 0) {
        int acc = 0;
        for (int i = 0; i < nb; i++) { soff2[i] = acc; acc += scnt[i]; }
        s_tot = (acc < MAXCAND) ? acc : MAXCAND;
    }
    __syncthreads();
    int tot = s_tot;
    if (t < nb) {
        int off = soff2[t], st = sstart[t], cn = scnt[t];
        for (int k = 0; k < cn; k++)
            if (off + k < MAXCAND) slist[off + k] = g_binSamples[st + k];
    }
    __syncthreads();
    for (int i = t; i < tot; i += 192) {
        int n = slist[i];
        int cpx = g_cells[n][0], cpy = g_cells[n][1], cpz = g_cells[n][2];
        float wx = 0.f, wy = 0.f, wz = 0.f;
        #pragma unroll
        for (int u = 0; u < 4; u++) {
            if (((cpx >> (8*u)) & 255) == ix) wx += g_w[n][u];
            if (((cpy >> (8*u)) & 255) == iy) wy += g_w[n][4 + u];
            if (((cpz >> (8*u)) & 255) == iz) wz += g_w[n][8 + u];
        }
        scand[i] = make_float2(wx * wy * wz, __int_as_float(n * DD));
    }
    __syncthreads();
    int d4 = t * 4;
    const __half* Wp = g_wgt + d4;
    float ax = 0.f, ay = 0.f, az = 0.f, aw = 0.f;
    for (int i = 0; i < tot; i++) {
        float2 ca = scand[i];
        float cf = ca.x;
        uint2 u = *reinterpret_cast<const uint2*>(Wp + __float_as_int(ca.y));
        float2 f0 = __half22float2(*reinterpret_cast<const __half2*>(&u.x));
        float2 f1 = __half22float2(*reinterpret_cast<const __half2*>(&u.y));
        ax += cf * f0.x; ay += cf * f0.y; az += cf * f1.x; aw += cf * f1.y;
    }
    float4 o; o.x = ax; o.y = ay; o.z = az; o.w = aw;
    *reinterpret_cast<float4*>(g_A + c*DD + d4) = o;
}

/* ---------------- K4: out partials = sum_c A[c,d]*E[c,h,d] ---------------- */
__global__ void __launch_bounds__(192, 2) k_out(const float* __restrict__ E) {
    int cg = blockIdx.x >> 1;
    int hg = blockIdx.x & 1;
    int t = threadIdx.x;
    int d4 = t * 4;
    float4 acc[HH];
    #pragma unroll
    for (int h = 0; h < HH; h++) { acc[h].x=0.f; acc[h].y=0.f; acc[h].z=0.f; acc[h].w=0.f; }

    for (int c = cg; c < NCELL; c += K4_CG) {
        float4 a = *reinterpret_cast<const float4*>(g_A + c*DD + d4);
        if (a.x == 0.f && a.y == 0.f && a.z == 0.f && a.w == 0.f) continue;
        const float4* base = reinterpret_cast<const float4*>(E + c*(CHH*DD) + hg*HH*DD + d4);
        #pragma unroll
        for (int h = 0; h < HH; h++) {
            float4 e = __ldcs(base + h*(DD/4));
            acc[h].x += a.x * e.x;
            acc[h].y += a.y * e.y;
            acc[h].z += a.z * e.z;
            acc[h].w += a.w * e.w;
        }
    }
    float* pb = g_part + blockIdx.x * (HH*DD);
    #pragma unroll
    for (int h = 0; h < HH; h++)
        *reinterpret_cast<float4*>(pb + h*DD + d4) = acc[h];
}

/* ---------------- K5: reduce partials -> d_out ---------------------------- */
__global__ void k_reduce(float* __restrict__ out) {
    int idx = blockIdx.x * blockDim.x + threadIdx.x;   /* 5760 threads */
    if (idx >= (NHH * DD) / 4) return;
    int h  = idx / (DD/4);
    int d4 = (idx - h*(DD/4)) * 4;
    int g  = h / HH;
    int hh = h - g*HH;
    float ax=0.f, ay=0.f, az=0.f, aw=0.f;
    #pragma unroll 4
    for (int cg = 0; cg < K4_CG; cg++) {
        const float4 v = *reinterpret_cast<const float4*>(
            g_part + (cg*2 + g) * (HH*DD) + hh*DD + d4);
        ax += v.x; ay += v.y; az += v.z; aw += v.w;
    }
    float4 o; o.x=ax; o.y=ay; o.z=az; o.w=aw;
    *reinterpret_cast<float4*>(out + h*DD + d4) = o;
}

/* ---------------- launcher ------------------------------------------------ */
extern "C" void kernel_launch(void* const* d_in, const int* in_sizes, int n_in,
                              void* d_out, int out_size) {
    const float* samples = (const float*)d_in[0];
    const float* lastp   = (const float*)d_in[1];
    const float* E       = (const float*)d_in[2];
    for (int i = 0; i < n_in; i++) {
        if (in_sizes[i] == NS * 3)            samples = (const float*)d_in[i];
        else if (in_sizes[i] == 3)            lastp   = (const float*)d_in[i];
        else if (in_sizes[i] > 1000000)       E       = (const float*)d_in[i];
    }

    k_init    <<<(NCELL*DD + 255)/256, 256>>>(E);
    k_prep    <<<(NS + 255)/256, 256>>>(samples, lastp);
    k_build   <<<1, 1024>>>();
    k_density <<<NS, 192>>>();
    k_chunksum<<<(NCHUNK*DD)/256, 256>>>();
    k_wgt     <<<(NCHUNK*DD)/256, 256>>>();
    k_A       <<<NCELL, 192>>>();
    k_out     <<<K4_GRID, 192>>>(E);
    k_reduce  <<<30, 192>>>((float*)d_out);
    (void)out_size;
}

// round 5
// speedup vs baseline: 1.2334x; 1.1524x over previous
#include <cuda_runtime.h>
#include <cuda_fp16.h>
#include <math.h>

#define GD     17
#define NS     4096
#define DD     768
#define NHH    30
#define CHH    31
#define NCELL  4913      /* 17^3 */
#define NCHUNK 64
#define CHUNK  64
#define K4_CG  296
#define K4_GRID (K4_CG*2)
#define HH     15        /* h per group */
#define MAXCAND 1536

/* ---------------- scratch (static device globals: allocation-free) ------- */
__device__ __align__(16) float  g_w[NS][12];
__device__              int    g_cells[NS][3];
__device__              float  g_dist[NS];
__device__              int    g_bin[NS];
__device__              int    g_binCount[NCELL];
__device__              int    g_binStart[NCELL + 1];
__device__              int    g_binCursor[NCELL];
__device__              int    g_binSamples[NS];
__device__              int    g_alive[NS];
__device__              int    g_cellAlive[NCELL];
__device__ __align__(16) __half g_Ed[NCELL * DD];      /* fp16 density slice */
__device__ __align__(16) float  g_sd[NS * DD];          /* fp32: scan precision */
__device__ __align__(16) __half g_wgt[NS * DD];         /* fp16 weights */
__device__ __align__(16) float  g_S[NCHUNK * DD];
__device__ __align__(16) float  g_A[NCELL * DD];
__device__ __align__(16) float  g_part[K4_GRID * HH * DD];

/* ---------------- K-init: clear flags + fp16-convert density ------------- */
__global__ void k_init(const float* __restrict__ E) {
    int i = blockIdx.x * blockDim.x + threadIdx.x;
    if (i < NCELL) g_binCount[i] = 0;
    if (i < NS)    g_alive[i] = 0;
    if (i < NCELL * DD) {
        int cell = i / DD;
        int d    = i - cell * DD;
        g_Ed[i] = __float2half(E[cell * (CHH*DD) + NHH*DD + d]);
    }
}

/* ---------------- K0: per-sample prep (weights, cells, dist, bin) -------- */
__global__ void k_prep(const float* __restrict__ samples,
                       const float* __restrict__ lastp) {
    int n = blockIdx.x * blockDim.x + threadIdx.x;
    if (n >= NS) return;

    float s[3] = { samples[3*n], samples[3*n+1], samples[3*n+2] };
    float nx[3];
    if (n < NS - 1) { nx[0]=samples[3*n+3]; nx[1]=samples[3*n+4]; nx[2]=samples[3*n+5]; }
    else            { nx[0]=lastp[0];       nx[1]=lastp[1];       nx[2]=lastp[2]; }
    float e0=s[0]-nx[0], e1=s[1]-nx[1], e2=s[2]-nx[2];
    g_dist[n] = sqrtf(e0*e0 + e1*e1 + e2*e2);

    int fi[3];
    #pragma unroll
    for (int a = 0; a < 3; a++) {
        float p  = s[a] + 8.0f;
        float f  = floorf(p);
        int  fii = (int)f;
        float dd = p - f;
        int  q   = (a == 0) ? (fii + 1) : (int)ceilf(p);   /* x uses f+1; y,z use ceil */
        int c0 = fii;
        int c1 = min(q, GD - 1);
        int c2 = max(fii - 1, 0);
        int c3 = min(q + 1, GD - 1);
        float mlo = (fii > 0)      ? 1.0f : 0.0f;
        float mhi = (fii + 2 < GD) ? 1.0f : 0.0f;
        float inv = 1.0f / (2.0f + mlo + mhi);
        g_w[n][a*4+0] = (2.0f - dd) * inv;
        g_w[n][a*4+1] = (1.0f + dd) * inv;
        g_w[n][a*4+2] = (1.0f - dd) * mlo * inv;
        g_w[n][a*4+3] = dd * mhi * inv;
        g_cells[n][a] = c0 | (c1 << 8) | (c2 << 16) | (c3 << 24);
        fi[a] = fii;
    }
    int bin = (fi[0]*GD + fi[1])*GD + fi[2];
    g_bin[n] = bin;
    atomicAdd(&g_binCount[bin], 1);
}

/* ---------------- K-build: warp-shuffle scan + scatter + sort ------------ */
__global__ void k_build() {
    int t = threadIdx.x;                   /* 1024 threads */
    int vals[5]; int s = 0;
    #pragma unroll
    for (int k = 0; k < 5; k++) {
        int idx = t*5 + k;
        int v = (idx < NCELL) ? g_binCount[idx] : 0;
        vals[k] = v; s += v;
    }
    int lane = t & 31, wid = t >> 5;
    int inc = s;
    #pragma unroll
    for (int off = 1; off < 32; off <<= 1) {
        int x = __shfl_up_sync(0xffffffffu, inc, off);
        if (lane >= off) inc += x;
    }
    __shared__ int wsum[32];
    if (lane == 31) wsum[wid] = inc;
    __syncthreads();
    if (wid == 0) {
        int v = wsum[lane];
        #pragma unroll
        for (int off = 1; off < 32; off <<= 1) {
            int x = __shfl_up_sync(0xffffffffu, v, off);
            if (lane >= off) v += x;
        }
        wsum[lane] = v;
    }
    __syncthreads();
    int base = inc - s + ((wid > 0) ? wsum[wid-1] : 0);
    #pragma unroll
    for (int k = 0; k < 5; k++) {
        int idx = t*5 + k;
        if (idx < NCELL) {
            g_binStart[idx]  = base;
            g_binCursor[idx] = base;
            base += vals[k];
        }
    }
    if (t == 0) g_binStart[NCELL] = NS;
    __syncthreads();
    for (int n = t; n < NS; n += 1024) {
        int pos = atomicAdd(&g_binCursor[g_bin[n]], 1);
        g_binSamples[pos] = n;
    }
    __syncthreads();
    for (int b = t; b < NCELL; b += 1024) {
        int s0 = g_binStart[b], s1 = g_binStart[b + 1];
        for (int i = s0 + 1; i < s1; i++) {
            int v = g_binSamples[i];
            int j = i - 1;
            while (j >= s0 && g_binSamples[j] > v) { g_binSamples[j+1] = g_binSamples[j]; j--; }
            g_binSamples[j + 1] = v;
        }
    }
}

/* ---------------- K1: density interp (fp16 table, 4d/thread) ------------- */
__global__ void __launch_bounds__(192) k_density() {
    __shared__ float2 sco[64];             /* (coef, offset-as-int) */
    __shared__ float  sw[12];
    __shared__ int    sc[3];
    int n = blockIdx.x;
    int t = threadIdx.x;
    if (t < 12) sw[t] = g_w[n][t];
    if (t < 3)  sc[t] = g_cells[n][t];
    __syncthreads();
    if (t < 64) {
        int i = t >> 4, j = (t >> 2) & 3, k = t & 3;
        int cx = (sc[0] >> (8*i)) & 255;
        int cy = (sc[1] >> (8*j)) & 255;
        int cz = (sc[2] >> (8*k)) & 255;
        float c = sw[i] * sw[4 + j] * sw[8 + k];
        int off = ((cx*GD + cy)*GD + cz) * DD;
        sco[t] = make_float2(c, __int_as_float(off));
    }
    __syncthreads();
    int d4 = t * 4;
    const __half* Ep = g_Ed + d4;
    float ax = 0.f, ay = 0.f, az = 0.f, aw = 0.f;
    #pragma unroll 4
    for (int m = 0; m < 64; m++) {
        float2 co = sco[m];
        float c = co.x;
        uint2 u = *reinterpret_cast<const uint2*>(Ep + __float_as_int(co.y));
        float2 f0 = __half22float2(*reinterpret_cast<const __half2*>(&u.x));
        float2 f1 = __half22float2(*reinterpret_cast<const __half2*>(&u.y));
        ax += c * f0.x; ay += c * f0.y; az += c * f1.x; aw += c * f1.y;
    }
    float dist = g_dist[n];
    float4 o;
    o.x = fmaxf(ax, 0.f) * dist;
    o.y = fmaxf(ay, 0.f) * dist;
    o.z = fmaxf(az, 0.f) * dist;
    o.w = fmaxf(aw, 0.f) * dist;
    *reinterpret_cast<float4*>(g_sd + n*DD + d4) = o;
}

/* ---------------- K2a: chunk partial sums of sd --------------------------- */
__global__ void k_chunksum() {
    int idx = blockIdx.x * blockDim.x + threadIdx.x;   /* NCHUNK*DD threads */
    int chunk = idx / DD;
    int d = idx - chunk * DD;
    int base = chunk * CHUNK * DD + d;
    float s = 0.f;
    #pragma unroll 8
    for (int i = 0; i < CHUNK; i++) s += g_sd[base + i*DD];
    g_S[chunk*DD + d] = s;
}

/* ---------------- K2b: scan + weights + alive flags ----------------------- */
__global__ void k_wgt() {
    int idx = blockIdx.x * blockDim.x + threadIdx.x;
    int chunk = idx / DD;
    int d = idx - chunk * DD;
    float excl = 0.f;
    for (int j = 0; j < chunk; j++) excl += g_S[j*DD + d];
    float T = __expf(-excl);                 /* one exp to seed the chunk */
    int base = chunk * CHUNK * DD + d;
    int n0 = chunk * CHUNK;
    for (int i = 0; i < CHUNK; i++) {
        float sd = g_sd[base + i*DD];
        float e  = __expf(-sd);              /* exp(-sd): alpha AND T-update */
        __half hv = __float2half(T * (1.0f - e));
        g_wgt[base + i*DD] = hv;
        if (__half_as_ushort(hv) != 0) g_alive[n0 + i] = 1;  /* idempotent */
        T *= e;
    }
}

/* ---------------- K3: A[c,d] gather (alive-filtered, deterministic) ------- */
__global__ void __launch_bounds__(192) k_A() {
    __shared__ int    slist[MAXCAND];
    __shared__ float2 scand[MAXCAND];      /* (coef, offset-as-int) */
    __shared__ int   scnt[64];
    __shared__ int   soff2[64];
    __shared__ int   sstart[64];
    __shared__ int   s_tot;
    int c = blockIdx.x;
    int iz = c % GD; int r = c / GD; int iy = r % GD; int ix = r / GD;
    int x0 = max(ix-2,0), x1 = min(ix+1,GD-1);
    int y0 = max(iy-2,0), y1 = min(iy+1,GD-1);
    int z0 = max(iz-2,0), z1 = min(iz+1,GD-1);
    int nxb = x1-x0+1, nyb = y1-y0+1, nzb = z1-z0+1;
    int nb = nxb * nyb * nzb;
    int t = threadIdx.x;

    /* per-bin count of ALIVE samples (order-preserving filter) */
    if (t < nb) {
        int bi = t / (nyb*nzb); int rr = t - bi*(nyb*nzb);
        int bj = rr / nzb;      int bk = rr - bj*nzb;
        int b = ((x0+bi)*GD + (y0+bj))*GD + (z0+bk);
        int st = g_binStart[b], en = g_binStart[b+1];
        sstart[t] = st;
        int cnt = 0;
        for (int k = st; k < en; k++)
            cnt += g_alive[g_binSamples[k]];
        scnt[t] = cnt;
    }
    __syncthreads();
    if (t == 0) {
        int acc = 0;
        for (int i = 0; i < nb; i++) { soff2[i] = acc; acc += scnt[i]; }
        s_tot = (acc < MAXCAND) ? acc : MAXCAND;
    }
    __syncthreads();
    int tot = s_tot;
    if (t == 0) g_cellAlive[c] = (tot > 0) ? 1 : 0;
    if (tot == 0) return;                   /* dead cell: A never read */
    if (t < nb) {
        int off = soff2[t], st = sstart[t];
        int en = st + 0;
        /* recompute end from binStart structure: walk until count consumed */
        int need = scnt[t];
        int k = st;
        while (need > 0) {
            int n = g_binSamples[k++];
            if (g_alive[n]) {
                if (off < MAXCAND) slist[off] = n;
                off++; need--;
            }
        }
        (void)en;
    }
    __syncthreads();
    for (int i = t; i < tot; i += 192) {
        int n = slist[i];
        int cpx = g_cells[n][0], cpy = g_cells[n][1], cpz = g_cells[n][2];
        float wx = 0.f, wy = 0.f, wz = 0.f;
        #pragma unroll
        for (int u = 0; u < 4; u++) {
            if (((cpx >> (8*u)) & 255) == ix) wx += g_w[n][u];
            if (((cpy >> (8*u)) & 255) == iy) wy += g_w[n][4 + u];
            if (((cpz >> (8*u)) & 255) == iz) wz += g_w[n][8 + u];
        }
        scand[i] = make_float2(wx * wy * wz, __int_as_float(n * DD));
    }
    __syncthreads();
    int d4 = t * 4;
    const __half* Wp = g_wgt + d4;
    float ax = 0.f, ay = 0.f, az = 0.f, aw = 0.f;
    for (int i = 0; i < tot; i++) {
        float2 ca = scand[i];
        float cf = ca.x;
        uint2 u = *reinterpret_cast<const uint2*>(Wp + __float_as_int(ca.y));
        float2 f0 = __half22float2(*reinterpret_cast<const __half2*>(&u.x));
        float2 f1 = __half22float2(*reinterpret_cast<const __half2*>(&u.y));
        ax += cf * f0.x; ay += cf * f0.y; az += cf * f1.x; aw += cf * f1.y;
    }
    float4 o; o.x = ax; o.y = ay; o.z = az; o.w = aw;
    *reinterpret_cast<float4*>(g_A + c*DD + d4) = o;
}

/* ---------------- K4: out partials, skipping dead cells ------------------- */
__global__ void __launch_bounds__(192, 2) k_out(const float* __restrict__ E) {
    int cg = blockIdx.x >> 1;
    int hg = blockIdx.x & 1;
    int t = threadIdx.x;
    int d4 = t * 4;
    float4 acc[HH];
    #pragma unroll
    for (int h = 0; h < HH; h++) { acc[h].x=0.f; acc[h].y=0.f; acc[h].z=0.f; acc[h].w=0.f; }

    for (int c = cg; c < NCELL; c += K4_CG) {
        if (__ldg(&g_cellAlive[c]) == 0) continue;
        float4 a = *reinterpret_cast<const float4*>(g_A + c*DD + d4);
        if (a.x == 0.f && a.y == 0.f && a.z == 0.f && a.w == 0.f) continue;
        const float4* base = reinterpret_cast<const float4*>(E + c*(CHH*DD) + hg*HH*DD + d4);
        #pragma unroll
        for (int h = 0; h < HH; h++) {
            float4 e = __ldcs(base + h*(DD/4));
            acc[h].x += a.x * e.x;
            acc[h].y += a.y * e.y;
            acc[h].z += a.z * e.z;
            acc[h].w += a.w * e.w;
        }
    }
    float* pb = g_part + blockIdx.x * (HH*DD);
    #pragma unroll
    for (int h = 0; h < HH; h++)
        *reinterpret_cast<float4*>(pb + h*DD + d4) = acc[h];
}

/* ---------------- K5: reduce partials -> d_out ---------------------------- */
__global__ void k_reduce(float* __restrict__ out) {
    int idx = blockIdx.x * blockDim.x + threadIdx.x;   /* 5760 threads */
    if (idx >= (NHH * DD) / 4) return;
    int h  = idx / (DD/4);
    int d4 = (idx - h*(DD/4)) * 4;
    int g  = h / HH;
    int hh = h - g*HH;
    float ax=0.f, ay=0.f, az=0.f, aw=0.f;
    #pragma unroll 4
    for (int cg = 0; cg < K4_CG; cg++) {
        const float4 v = *reinterpret_cast<const float4*>(
            g_part + (cg*2 + g) * (HH*DD) + hh*DD + d4);
        ax += v.x; ay += v.y; az += v.z; aw += v.w;
    }
    float4 o; o.x=ax; o.y=ay; o.z=az; o.w=aw;
    *reinterpret_cast<float4*>(out + h*DD + d4) = o;
}

/* ---------------- launcher ------------------------------------------------ */
extern "C" void kernel_launch(void* const* d_in, const int* in_sizes, int n_in,
                              void* d_out, int out_size) {
    const float* samples = (const float*)d_in[0];
    const float* lastp   = (const float*)d_in[1];
    const float* E       = (const float*)d_in[2];
    for (int i = 0; i < n_in; i++) {
        if (in_sizes[i] == NS * 3)            samples = (const float*)d_in[i];
        else if (in_sizes[i] == 3)            lastp   = (const float*)d_in[i];
        else if (in_sizes[i] > 1000000)       E       = (const float*)d_in[i];
    }

    k_init    <<<(NCELL*DD + 255)/256, 256>>>(E);
    k_prep    <<<(NS + 255)/256, 256>>>(samples, lastp);
    k_build   <<<1, 1024>>>();
    k_density <<<NS, 192>>>();
    k_chunksum<<<(NCHUNK*DD)/256, 256>>>();
    k_wgt     <<<(NCHUNK*DD)/256, 256>>>();
    k_A       <<<NCELL, 192>>>();
    k_out     <<<K4_GRID, 192>>>(E);
    k_reduce  <<<30, 192>>>((float*)d_out);
    (void)out_size;
}

// round 6
// speedup vs baseline: 1.2741x; 1.0330x over previous
#include <cuda_runtime.h>
#include <cuda_fp16.h>
#include <math.h>

#define GD     17
#define NS     4096
#define DD     768
#define NHH    30
#define CHH    31
#define NCELL  4913      /* 17^3 */
#define FRONT  128
#define K4_CG  296
#define K4_GRID (K4_CG*2)
#define HH     15        /* h per group */
#define MAXCAND 1536

/* ---------------- scratch (static device globals: allocation-free) ------- */
__device__ __align__(16) float  g_w[NS][12];
__device__              int    g_cells[NS][3];
__device__              float  g_dist[NS];
__device__              int    g_bin[NS];
__device__              int    g_binCount[NCELL];
__device__              int    g_binStart[NCELL + 1];
__device__              int    g_binCursor[NCELL];
__device__              int    g_binSamples[NS];
__device__              int    g_alive[NS];
__device__              int    g_cellAlive[NCELL];
__device__              int    g_need;
__device__              float  g_T128[DD];
__device__ __align__(16) __half g_Ed[NCELL * DD];      /* fp16 density slice */
__device__ __align__(16) float  g_sd[NS * DD];          /* fp32 density*dist */
__device__ __align__(16) __half g_wgt[NS * DD];         /* fp16 weights */
__device__ __align__(16) float  g_A[NCELL * DD];
__device__ __align__(16) float  g_part[K4_GRID * HH * DD];

/* ---------------- K-init: clear flags + fp16-convert density ------------- */
__global__ void k_init(const float* __restrict__ E) {
    int i = blockIdx.x * blockDim.x + threadIdx.x;
    if (i < NCELL) g_binCount[i] = 0;
    if (i < NS)    g_alive[i] = 0;
    if (i == 0)    g_need = 0;
    if (i < NCELL * DD) {
        int cell = i / DD;
        int d    = i - cell * DD;
        g_Ed[i] = __float2half(E[cell * (CHH*DD) + NHH*DD + d]);
    }
}

/* ---------------- K0: per-sample prep (weights, cells, dist, bin) -------- */
__global__ void k_prep(const float* __restrict__ samples,
                       const float* __restrict__ lastp) {
    int n = blockIdx.x * blockDim.x + threadIdx.x;
    if (n >= NS) return;

    float s[3] = { samples[3*n], samples[3*n+1], samples[3*n+2] };
    float nx[3];
    if (n < NS - 1) { nx[0]=samples[3*n+3]; nx[1]=samples[3*n+4]; nx[2]=samples[3*n+5]; }
    else            { nx[0]=lastp[0];       nx[1]=lastp[1];       nx[2]=lastp[2]; }
    float e0=s[0]-nx[0], e1=s[1]-nx[1], e2=s[2]-nx[2];
    g_dist[n] = sqrtf(e0*e0 + e1*e1 + e2*e2);

    int fi[3];
    #pragma unroll
    for (int a = 0; a < 3; a++) {
        float p  = s[a] + 8.0f;
        float f  = floorf(p);
        int  fii = (int)f;
        float dd = p - f;
        int  q   = (a == 0) ? (fii + 1) : (int)ceilf(p);   /* x uses f+1; y,z use ceil */
        int c0 = fii;
        int c1 = min(q, GD - 1);
        int c2 = max(fii - 1, 0);
        int c3 = min(q + 1, GD - 1);
        float mlo = (fii > 0)      ? 1.0f : 0.0f;
        float mhi = (fii + 2 < GD) ? 1.0f : 0.0f;
        float inv = 1.0f / (2.0f + mlo + mhi);
        g_w[n][a*4+0] = (2.0f - dd) * inv;
        g_w[n][a*4+1] = (1.0f + dd) * inv;
        g_w[n][a*4+2] = (1.0f - dd) * mlo * inv;
        g_w[n][a*4+3] = dd * mhi * inv;
        g_cells[n][a] = c0 | (c1 << 8) | (c2 << 16) | (c3 << 24);
        fi[a] = fii;
    }
    int bin = (fi[0]*GD + fi[1])*GD + fi[2];
    g_bin[n] = bin;
    atomicAdd(&g_binCount[bin], 1);
}

/* ---------------- K-build: warp-shuffle scan + scatter + sort ------------ */
__global__ void k_build() {
    int t = threadIdx.x;                   /* 1024 threads */
    int vals[5]; int s = 0;
    #pragma unroll
    for (int k = 0; k < 5; k++) {
        int idx = t*5 + k;
        int v = (idx < NCELL) ? g_binCount[idx] : 0;
        vals[k] = v; s += v;
    }
    int lane = t & 31, wid = t >> 5;
    int inc = s;
    #pragma unroll
    for (int off = 1; off < 32; off <<= 1) {
        int x = __shfl_up_sync(0xffffffffu, inc, off);
        if (lane >= off) inc += x;
    }
    __shared__ int wsum[32];
    if (lane == 31) wsum[wid] = inc;
    __syncthreads();
    if (wid == 0) {
        int v = wsum[lane];
        #pragma unroll
        for (int off = 1; off < 32; off <<= 1) {
            int x = __shfl_up_sync(0xffffffffu, v, off);
            if (lane >= off) v += x;
        }
        wsum[lane] = v;
    }
    __syncthreads();
    int base = inc - s + ((wid > 0) ? wsum[wid-1] : 0);
    #pragma unroll
    for (int k = 0; k < 5; k++) {
        int idx = t*5 + k;
        if (idx < NCELL) {
            g_binStart[idx]  = base;
            g_binCursor[idx] = base;
            base += vals[k];
        }
    }
    if (t == 0) g_binStart[NCELL] = NS;
    __syncthreads();
    for (int n = t; n < NS; n += 1024) {
        int pos = atomicAdd(&g_binCursor[g_bin[n]], 1);
        g_binSamples[pos] = n;
    }
    __syncthreads();
    for (int b = t; b < NCELL; b += 1024) {
        int s0 = g_binStart[b], s1 = g_binStart[b + 1];
        for (int i = s0 + 1; i < s1; i++) {
            int v = g_binSamples[i];
            int j = i - 1;
            while (j >= s0 && g_binSamples[j] > v) { g_binSamples[j+1] = g_binSamples[j]; j--; }
            g_binSamples[j + 1] = v;
        }
    }
}

/* ---------------- density interp body (shared by front/rest) ------------- */
__device__ __forceinline__ void density_body(int n, int t,
                                             float2* sco, float* sw, int* sc) {
    if (t < 12) sw[t] = g_w[n][t];
    if (t < 3)  sc[t] = g_cells[n][t];
    __syncthreads();
    if (t < 64) {
        int i = t >> 4, j = (t >> 2) & 3, k = t & 3;
        int cx = (sc[0] >> (8*i)) & 255;
        int cy = (sc[1] >> (8*j)) & 255;
        int cz = (sc[2] >> (8*k)) & 255;
        float c = sw[i] * sw[4 + j] * sw[8 + k];
        int off = ((cx*GD + cy)*GD + cz) * DD;
        sco[t] = make_float2(c, __int_as_float(off));
    }
    __syncthreads();
    int d4 = t * 4;
    const __half* Ep = g_Ed + d4;
    float ax = 0.f, ay = 0.f, az = 0.f, aw = 0.f;
    #pragma unroll 4
    for (int m = 0; m < 64; m++) {
        float2 co = sco[m];
        float c = co.x;
        uint2 u = *reinterpret_cast<const uint2*>(Ep + __float_as_int(co.y));
        float2 f0 = __half22float2(*reinterpret_cast<const __half2*>(&u.x));
        float2 f1 = __half22float2(*reinterpret_cast<const __half2*>(&u.y));
        ax += c * f0.x; ay += c * f0.y; az += c * f1.x; aw += c * f1.y;
    }
    float dist = g_dist[n];
    float4 o;
    o.x = fmaxf(ax, 0.f) * dist;
    o.y = fmaxf(ay, 0.f) * dist;
    o.z = fmaxf(az, 0.f) * dist;
    o.w = fmaxf(aw, 0.f) * dist;
    *reinterpret_cast<float4*>(g_sd + n*DD + d4) = o;
}

/* ---------------- K1a: density for first FRONT samples -------------------- */
__global__ void __launch_bounds__(192) k_density_front() {
    __shared__ float2 sco[64];
    __shared__ float  sw[12];
    __shared__ int    sc[3];
    density_body(blockIdx.x, threadIdx.x, sco, sw, sc);
}

/* ---------------- K1b: density for the rest (guarded, usually no-op) ------ */
__global__ void __launch_bounds__(192) k_density_rest() {
    if (!g_need) return;
    __shared__ float2 sco[64];
    __shared__ float  sw[12];
    __shared__ int    sc[3];
    density_body(FRONT + blockIdx.x, threadIdx.x, sco, sw, sc);
}

/* ---------------- K2a: front transmittance scan (serial per channel) ------ */
__global__ void k_wgt_front() {
    int d = blockIdx.x * blockDim.x + threadIdx.x;    /* DD threads total */
    if (d >= DD) return;
    float T = 1.0f;
    for (int n = 0; n < FRONT; n++) {
        float sd = g_sd[n*DD + d];
        float e  = __expf(-sd);
        __half hv = __float2half(T * (1.0f - e));
        g_wgt[n*DD + d] = hv;
        if (__half_as_ushort(hv) != 0) g_alive[n] = 1;  /* idempotent */
        T *= e;
    }
    g_T128[d] = T;
    /* safe-skip condition: all future wgt < T <= 2^-25 rounds to fp16 +0 */
    if (T > 0x1p-25f) atomicOr(&g_need, 1);
}

/* ---------------- K2b: rest scan (guarded, usually no-op) ----------------- */
__global__ void k_wgt_rest() {
    if (!g_need) return;
    int d = blockIdx.x * blockDim.x + threadIdx.x;
    if (d >= DD) return;
    float T = g_T128[d];
    for (int n = FRONT; n < NS; n++) {
        float sd = g_sd[n*DD + d];
        float e  = __expf(-sd);
        __half hv = __float2half(T * (1.0f - e));
        g_wgt[n*DD + d] = hv;
        if (__half_as_ushort(hv) != 0) g_alive[n] = 1;
        T *= e;
    }
}

/* ---------------- K3: A[c,d] gather (alive-filtered, deterministic) ------- */
__global__ void __launch_bounds__(192) k_A() {
    __shared__ int    slist[MAXCAND];
    __shared__ float2 scand[MAXCAND];      /* (coef, offset-as-int) */
    __shared__ int   scnt[64];
    __shared__ int   soff2[64];
    __shared__ int   sstart[64];
    __shared__ int   s_tot;
    int c = blockIdx.x;
    int iz = c % GD; int r = c / GD; int iy = r % GD; int ix = r / GD;
    int x0 = max(ix-2,0), x1 = min(ix+1,GD-1);
    int y0 = max(iy-2,0), y1 = min(iy+1,GD-1);
    int z0 = max(iz-2,0), z1 = min(iz+1,GD-1);
    int nxb = x1-x0+1, nyb = y1-y0+1, nzb = z1-z0+1;
    int nb = nxb * nyb * nzb;
    int t = threadIdx.x;

    if (t < nb) {
        int bi = t / (nyb*nzb); int rr = t - bi*(nyb*nzb);
        int bj = rr / nzb;      int bk = rr - bj*nzb;
        int b = ((x0+bi)*GD + (y0+bj))*GD + (z0+bk);
        int st = g_binStart[b], en = g_binStart[b+1];
        sstart[t] = st;
        int cnt = 0;
        for (int k = st; k < en; k++)
            cnt += g_alive[g_binSamples[k]];
        scnt[t] = cnt;
    }
    __syncthreads();
    if (t == 0) {
        int acc = 0;
        for (int i = 0; i < nb; i++) { soff2[i] = acc; acc += scnt[i]; }
        s_tot = (acc < MAXCAND) ? acc : MAXCAND;
    }
    __syncthreads();
    int tot = s_tot;
    if (t == 0) g_cellAlive[c] = (tot > 0) ? 1 : 0;
    if (tot == 0) return;                   /* dead cell: A never read */
    if (t < nb) {
        int off = soff2[t], st = sstart[t];
        int need = scnt[t];
        int k = st;
        while (need > 0) {
            int n = g_binSamples[k++];
            if (g_alive[n]) {
                if (off < MAXCAND) slist[off] = n;
                off++; need--;
            }
        }
    }
    __syncthreads();
    for (int i = t; i < tot; i += 192) {
        int n = slist[i];
        int cpx = g_cells[n][0], cpy = g_cells[n][1], cpz = g_cells[n][2];
        float wx = 0.f, wy = 0.f, wz = 0.f;
        #pragma unroll
        for (int u = 0; u < 4; u++) {
            if (((cpx >> (8*u)) & 255) == ix) wx += g_w[n][u];
            if (((cpy >> (8*u)) & 255) == iy) wy += g_w[n][4 + u];
            if (((cpz >> (8*u)) & 255) == iz) wz += g_w[n][8 + u];
        }
        scand[i] = make_float2(wx * wy * wz, __int_as_float(n * DD));
    }
    __syncthreads();
    int d4 = t * 4;
    const __half* Wp = g_wgt + d4;
    float ax = 0.f, ay = 0.f, az = 0.f, aw = 0.f;
    for (int i = 0; i < tot; i++) {
        float2 ca = scand[i];
        float cf = ca.x;
        uint2 u = *reinterpret_cast<const uint2*>(Wp + __float_as_int(ca.y));
        float2 f0 = __half22float2(*reinterpret_cast<const __half2*>(&u.x));
        float2 f1 = __half22float2(*reinterpret_cast<const __half2*>(&u.y));
        ax += cf * f0.x; ay += cf * f0.y; az += cf * f1.x; aw += cf * f1.y;
    }
    float4 o; o.x = ax; o.y = ay; o.z = az; o.w = aw;
    *reinterpret_cast<float4*>(g_A + c*DD + d4) = o;
}

/* ---------------- K4: out partials, skipping dead cells ------------------- */
__global__ void __launch_bounds__(192, 2) k_out(const float* __restrict__ E) {
    int cg = blockIdx.x >> 1;
    int hg = blockIdx.x & 1;
    int t = threadIdx.x;
    int d4 = t * 4;
    float4 acc[HH];
    #pragma unroll
    for (int h = 0; h < HH; h++) { acc[h].x=0.f; acc[h].y=0.f; acc[h].z=0.f; acc[h].w=0.f; }

    for (int c = cg; c < NCELL; c += K4_CG) {
        if (__ldg(&g_cellAlive[c]) == 0) continue;
        float4 a = *reinterpret_cast<const float4*>(g_A + c*DD + d4);
        if (a.x == 0.f && a.y == 0.f && a.z == 0.f && a.w == 0.f) continue;
        const float4* base = reinterpret_cast<const float4*>(E + c*(CHH*DD) + hg*HH*DD + d4);
        #pragma unroll
        for (int h = 0; h < HH; h++) {
            float4 e = __ldcs(base + h*(DD/4));
            acc[h].x += a.x * e.x;
            acc[h].y += a.y * e.y;
            acc[h].z += a.z * e.z;
            acc[h].w += a.w * e.w;
        }
    }
    float* pb = g_part + blockIdx.x * (HH*DD);
    #pragma unroll
    for (int h = 0; h < HH; h++)
        *reinterpret_cast<float4*>(pb + h*DD + d4) = acc[h];
}

/* ---------------- K5: reduce partials -> d_out ---------------------------- */
__global__ void k_reduce(float* __restrict__ out) {
    int idx = blockIdx.x * blockDim.x + threadIdx.x;   /* 5760 threads */
    if (idx >= (NHH * DD) / 4) return;
    int h  = idx / (DD/4);
    int d4 = (idx - h*(DD/4)) * 4;
    int g  = h / HH;
    int hh = h - g*HH;
    float ax=0.f, ay=0.f, az=0.f, aw=0.f;
    #pragma unroll 4
    for (int cg = 0; cg < K4_CG; cg++) {
        const float4 v = *reinterpret_cast<const float4*>(
            g_part + (cg*2 + g) * (HH*DD) + hh*DD + d4);
        ax += v.x; ay += v.y; az += v.z; aw += v.w;
    }
    float4 o; o.x=ax; o.y=ay; o.z=az; o.w=aw;
    *reinterpret_cast<float4*>(out + h*DD + d4) = o;
}

/* ---------------- launcher ------------------------------------------------ */
extern "C" void kernel_launch(void* const* d_in, const int* in_sizes, int n_in,
                              void* d_out, int out_size) {
    const float* samples = (const float*)d_in[0];
    const float* lastp   = (const float*)d_in[1];
    const float* E       = (const float*)d_in[2];
    for (int i = 0; i < n_in; i++) {
        if (in_sizes[i] == NS * 3)            samples = (const float*)d_in[i];
        else if (in_sizes[i] == 3)            lastp   = (const float*)d_in[i];
        else if (in_sizes[i] > 1000000)       E       = (const float*)d_in[i];
    }

    k_init          <<<(NCELL*DD + 255)/256, 256>>>(E);
    k_prep          <<<(NS + 255)/256, 256>>>(samples, lastp);
    k_build         <<<1, 1024>>>();
    k_density_front <<<FRONT, 192>>>();
    k_wgt_front     <<<4, 192>>>();
    k_density_rest  <<<NS - FRONT, 192>>>();
    k_wgt_rest      <<<4, 192>>>();
    k_A             <<<NCELL, 192>>>();
    k_out           <<<K4_GRID, 192>>>(E);
    k_reduce        <<<30, 192>>>((float*)d_out);
    (void)out_size;
}

// round 7
// speedup vs baseline: 1.7943x; 1.4083x over previous
#include <cuda_runtime.h>
#include <cuda_fp16.h>
#include <math.h>

#define GD     17
#define NS     4096
#define DD     768
#define NHH    30
#define CHH    31
#define NCELL  4913      /* 17^3 */
#define FRONT  128
#define K4_CG  148
#define K4_GRID (K4_CG*2)
#define HH     15        /* h per group */
#define MAXCAND 1536

/* ---------------- scratch (static device globals: allocation-free) ------- */
__device__ __align__(16) float  g_w[NS][12];
__device__              int    g_cells[NS][3];
__device__              float  g_dist[NS];
__device__              int    g_bin[NS];
__device__              int    g_binCount[NCELL];
__device__              int    g_binStart[NCELL + 1];
__device__              int    g_binCursor[NCELL];
__device__              int    g_binSamples[NS];
__device__              int    g_alive[NS];
__device__              int    g_cellAlive[NCELL];
__device__              int    g_aliveList[NCELL];
__device__              int    g_nAlive;
__device__              int    g_need;
__device__              float  g_T128[DD];
__device__ __align__(16) float  g_sd[NS * DD];          /* fp32 density*dist */
__device__ __align__(16) __half g_wgt[NS * DD];         /* fp16 weights */
__device__ __align__(16) float  g_A[NCELL * DD];
__device__ __align__(16) float  g_part[K4_GRID * HH * DD];

/* ---------------- K-init: clear flags ------------------------------------ */
__global__ void k_init() {
    int i = blockIdx.x * blockDim.x + threadIdx.x;
    if (i < NCELL) g_binCount[i] = 0;
    if (i < NS)    g_alive[i] = 0;
    if (i == 0)    g_need = 0;
}

/* ---------------- K0: per-sample prep (weights, cells, dist, bin) -------- */
__global__ void k_prep(const float* __restrict__ samples,
                       const float* __restrict__ lastp) {
    int n = blockIdx.x * blockDim.x + threadIdx.x;
    if (n >= NS) return;

    float s[3] = { samples[3*n], samples[3*n+1], samples[3*n+2] };
    float nx[3];
    if (n < NS - 1) { nx[0]=samples[3*n+3]; nx[1]=samples[3*n+4]; nx[2]=samples[3*n+5]; }
    else            { nx[0]=lastp[0];       nx[1]=lastp[1];       nx[2]=lastp[2]; }
    float e0=s[0]-nx[0], e1=s[1]-nx[1], e2=s[2]-nx[2];
    g_dist[n] = sqrtf(e0*e0 + e1*e1 + e2*e2);

    int fi[3];
    #pragma unroll
    for (int a = 0; a < 3; a++) {
        float p  = s[a] + 8.0f;
        float f  = floorf(p);
        int  fii = (int)f;
        float dd = p - f;
        int  q   = (a == 0) ? (fii + 1) : (int)ceilf(p);   /* x uses f+1; y,z use ceil */
        int c0 = fii;
        int c1 = min(q, GD - 1);
        int c2 = max(fii - 1, 0);
        int c3 = min(q + 1, GD - 1);
        float mlo = (fii > 0)      ? 1.0f : 0.0f;
        float mhi = (fii + 2 < GD) ? 1.0f : 0.0f;
        float inv = 1.0f / (2.0f + mlo + mhi);
        g_w[n][a*4+0] = (2.0f - dd) * inv;
        g_w[n][a*4+1] = (1.0f + dd) * inv;
        g_w[n][a*4+2] = (1.0f - dd) * mlo * inv;
        g_w[n][a*4+3] = dd * mhi * inv;
        g_cells[n][a] = c0 | (c1 << 8) | (c2 << 16) | (c3 << 24);
        fi[a] = fii;
    }
    int bin = (fi[0]*GD + fi[1])*GD + fi[2];
    g_bin[n] = bin;
    atomicAdd(&g_binCount[bin], 1);
}

/* ---------------- K-build: warp-shuffle scan + scatter + sort ------------ */
__global__ void k_build() {
    int t = threadIdx.x;                   /* 1024 threads */
    int vals[5]; int s = 0;
    #pragma unroll
    for (int k = 0; k < 5; k++) {
        int idx = t*5 + k;
        int v = (idx < NCELL) ? g_binCount[idx] : 0;
        vals[k] = v; s += v;
    }
    int lane = t & 31, wid = t >> 5;
    int inc = s;
    #pragma unroll
    for (int off = 1; off < 32; off <<= 1) {
        int x = __shfl_up_sync(0xffffffffu, inc, off);
        if (lane >= off) inc += x;
    }
    __shared__ int wsum[32];
    if (lane == 31) wsum[wid] = inc;
    __syncthreads();
    if (wid == 0) {
        int v = wsum[lane];
        #pragma unroll
        for (int off = 1; off < 32; off <<= 1) {
            int x = __shfl_up_sync(0xffffffffu, v, off);
            if (lane >= off) v += x;
        }
        wsum[lane] = v;
    }
    __syncthreads();
    int base = inc - s + ((wid > 0) ? wsum[wid-1] : 0);
    #pragma unroll
    for (int k = 0; k < 5; k++) {
        int idx = t*5 + k;
        if (idx < NCELL) {
            g_binStart[idx]  = base;
            g_binCursor[idx] = base;
            base += vals[k];
        }
    }
    if (t == 0) g_binStart[NCELL] = NS;
    __syncthreads();
    for (int n = t; n < NS; n += 1024) {
        int pos = atomicAdd(&g_binCursor[g_bin[n]], 1);
        g_binSamples[pos] = n;
    }
    __syncthreads();
    for (int b = t; b < NCELL; b += 1024) {
        int s0 = g_binStart[b], s1 = g_binStart[b + 1];
        for (int i = s0 + 1; i < s1; i++) {
            int v = g_binSamples[i];
            int j = i - 1;
            while (j >= s0 && g_binSamples[j] > v) { g_binSamples[j+1] = g_binSamples[j]; j--; }
            g_binSamples[j + 1] = v;
        }
    }
}

/* ---------------- density interp body (fp32 E, shared front/rest) -------- */
__device__ __forceinline__ void density_body(const float* __restrict__ E,
                                             int n, int t,
                                             float2* sco, float* sw, int* sc) {
    if (t < 12) sw[t] = g_w[n][t];
    if (t < 3)  sc[t] = g_cells[n][t];
    __syncthreads();
    if (t < 64) {
        int i = t >> 4, j = (t >> 2) & 3, k = t & 3;
        int cx = (sc[0] >> (8*i)) & 255;
        int cy = (sc[1] >> (8*j)) & 255;
        int cz = (sc[2] >> (8*k)) & 255;
        float c = sw[i] * sw[4 + j] * sw[8 + k];
        int off = ((cx*GD + cy)*GD + cz) * (CHH*DD) + NHH*DD;
        sco[t] = make_float2(c, __int_as_float(off));
    }
    __syncthreads();
    int d4 = t * 4;
    const float* Ep = E + d4;
    float ax = 0.f, ay = 0.f, az = 0.f, aw = 0.f;
    #pragma unroll 4
    for (int m = 0; m < 64; m++) {
        float2 co = sco[m];
        float c = co.x;
        float4 e = __ldg(reinterpret_cast<const float4*>(Ep + __float_as_int(co.y)));
        ax += c * e.x; ay += c * e.y; az += c * e.z; aw += c * e.w;
    }
    float dist = g_dist[n];
    float4 o;
    o.x = fmaxf(ax, 0.f) * dist;
    o.y = fmaxf(ay, 0.f) * dist;
    o.z = fmaxf(az, 0.f) * dist;
    o.w = fmaxf(aw, 0.f) * dist;
    *reinterpret_cast<float4*>(g_sd + n*DD + d4) = o;
}

/* ---------------- K1a: density for first FRONT samples -------------------- */
__global__ void __launch_bounds__(192) k_density_front(const float* __restrict__ E) {
    __shared__ float2 sco[64];
    __shared__ float  sw[12];
    __shared__ int    sc[3];
    density_body(E, blockIdx.x, threadIdx.x, sco, sw, sc);
}

/* ---------------- K1b: density for the rest (guarded, usually no-op) ------ */
__global__ void __launch_bounds__(192) k_density_rest(const float* __restrict__ E) {
    if (!g_need) return;
    __shared__ float2 sco[64];
    __shared__ float  sw[12];
    __shared__ int    sc[3];
    density_body(E, FRONT + blockIdx.x, threadIdx.x, sco, sw, sc);
}

/* ---------------- K2a: front transmittance scan (unroll-4, MLP) ----------- */
__global__ void k_wgt_front() {
    int d = blockIdx.x * blockDim.x + threadIdx.x;    /* DD threads total */
    if (d >= DD) return;
    float T = 1.0f;
    for (int n = 0; n < FRONT; n += 4) {
        float s0 = g_sd[(n+0)*DD + d];
        float s1 = g_sd[(n+1)*DD + d];
        float s2 = g_sd[(n+2)*DD + d];
        float s3 = g_sd[(n+3)*DD + d];
        float e0 = __expf(-s0), e1 = __expf(-s1);
        float e2 = __expf(-s2), e3 = __expf(-s3);
        __half h0 = __float2half(T * (1.0f - e0)); T *= e0;
        __half h1 = __float2half(T * (1.0f - e1)); T *= e1;
        __half h2 = __float2half(T * (1.0f - e2)); T *= e2;
        __half h3 = __float2half(T * (1.0f - e3)); T *= e3;
        g_wgt[(n+0)*DD + d] = h0;
        g_wgt[(n+1)*DD + d] = h1;
        g_wgt[(n+2)*DD + d] = h2;
        g_wgt[(n+3)*DD + d] = h3;
        if (__half_as_ushort(h0) != 0) g_alive[n+0] = 1;
        if (__half_as_ushort(h1) != 0) g_alive[n+1] = 1;
        if (__half_as_ushort(h2) != 0) g_alive[n+2] = 1;
        if (__half_as_ushort(h3) != 0) g_alive[n+3] = 1;
    }
    g_T128[d] = T;
    /* safe-skip condition: all future wgt < T <= 2^-25 rounds to fp16 +0 */
    if (T > 0x1p-25f) atomicOr(&g_need, 1);
}

/* ---------------- K2b: rest scan (guarded, usually no-op) ----------------- */
__global__ void k_wgt_rest() {
    if (!g_need) return;
    int d = blockIdx.x * blockDim.x + threadIdx.x;
    if (d >= DD) return;
    float T = g_T128[d];
    for (int n = FRONT; n < NS; n++) {
        float sd = g_sd[n*DD + d];
        float e  = __expf(-sd);
        __half hv = __float2half(T * (1.0f - e));
        g_wgt[n*DD + d] = hv;
        if (__half_as_ushort(hv) != 0) g_alive[n] = 1;
        T *= e;
    }
}

/* ---------------- K3: A[c,d] gather (alive-filtered, deterministic) ------- */
__global__ void __launch_bounds__(192) k_A() {
    __shared__ int    slist[MAXCAND];
    __shared__ float2 scand[MAXCAND];      /* (coef, offset-as-int) */
    __shared__ int   scnt[64];
    __shared__ int   soff2[64];
    __shared__ int   sstart[64];
    __shared__ int   s_tot;
    int c = blockIdx.x;
    int iz = c % GD; int r = c / GD; int iy = r % GD; int ix = r / GD;
    int x0 = max(ix-2,0), x1 = min(ix+1,GD-1);
    int y0 = max(iy-2,0), y1 = min(iy+1,GD-1);
    int z0 = max(iz-2,0), z1 = min(iz+1,GD-1);
    int nxb = x1-x0+1, nyb = y1-y0+1, nzb = z1-z0+1;
    int nb = nxb * nyb * nzb;
    int t = threadIdx.x;

    if (t < nb) {
        int bi = t / (nyb*nzb); int rr = t - bi*(nyb*nzb);
        int bj = rr / nzb;      int bk = rr - bj*nzb;
        int b = ((x0+bi)*GD + (y0+bj))*GD + (z0+bk);
        int st = g_binStart[b], en = g_binStart[b+1];
        sstart[t] = st;
        int cnt = 0;
        for (int k = st; k < en; k++)
            cnt += g_alive[g_binSamples[k]];
        scnt[t] = cnt;
    }
    __syncthreads();
    if (t == 0) {
        int acc = 0;
        for (int i = 0; i < nb; i++) { soff2[i] = acc; acc += scnt[i]; }
        s_tot = (acc < MAXCAND) ? acc : MAXCAND;
    }
    __syncthreads();
    int tot = s_tot;
    if (t == 0) g_cellAlive[c] = (tot > 0) ? 1 : 0;
    if (tot == 0) return;                   /* dead cell: A never read */
    if (t < nb) {
        int off = soff2[t], st = sstart[t];
        int need = scnt[t];
        int k = st;
        while (need > 0) {
            int n = g_binSamples[k++];
            if (g_alive[n]) {
                if (off < MAXCAND) slist[off] = n;
                off++; need--;
            }
        }
    }
    __syncthreads();
    for (int i = t; i < tot; i += 192) {
        int n = slist[i];
        int cpx = g_cells[n][0], cpy = g_cells[n][1], cpz = g_cells[n][2];
        float wx = 0.f, wy = 0.f, wz = 0.f;
        #pragma unroll
        for (int u = 0; u < 4; u++) {
            if (((cpx >> (8*u)) & 255) == ix) wx += g_w[n][u];
            if (((cpy >> (8*u)) & 255) == iy) wy += g_w[n][4 + u];
            if (((cpz >> (8*u)) & 255) == iz) wz += g_w[n][8 + u];
        }
        scand[i] = make_float2(wx * wy * wz, __int_as_float(n * DD));
    }
    __syncthreads();
    int d4 = t * 4;
    const __half* Wp = g_wgt + d4;
    float ax = 0.f, ay = 0.f, az = 0.f, aw = 0.f;
    for (int i = 0; i < tot; i++) {
        float2 ca = scand[i];
        float cf = ca.x;
        uint2 u = *reinterpret_cast<const uint2*>(Wp + __float_as_int(ca.y));
        float2 f0 = __half22float2(*reinterpret_cast<const __half2*>(&u.x));
        float2 f1 = __half22float2(*reinterpret_cast<const __half2*>(&u.y));
        ax += cf * f0.x; ay += cf * f0.y; az += cf * f1.x; aw += cf * f1.y;
    }
    float4 o; o.x = ax; o.y = ay; o.z = az; o.w = aw;
    *reinterpret_cast<float4*>(g_A + c*DD + d4) = o;
}

/* ---------------- K-compact: deterministic alive-cell list ---------------- */
__global__ void k_compact() {
    int t = threadIdx.x;                   /* 1024 threads */
    int vals[5]; int s = 0;
    #pragma unroll
    for (int k = 0; k < 5; k++) {
        int idx = t*5 + k;
        int v = (idx < NCELL) ? g_cellAlive[idx] : 0;
        vals[k] = v; s += v;
    }
    int lane = t & 31, wid = t >> 5;
    int inc = s;
    #pragma unroll
    for (int off = 1; off < 32; off <<= 1) {
        int x = __shfl_up_sync(0xffffffffu, inc, off);
        if (lane >= off) inc += x;
    }
    __shared__ int wsum[32];
    if (lane == 31) wsum[wid] = inc;
    __syncthreads();
    if (wid == 0) {
        int v = wsum[lane];
        #pragma unroll
        for (int off = 1; off < 32; off <<= 1) {
            int x = __shfl_up_sync(0xffffffffu, v, off);
            if (lane >= off) v += x;
        }
        wsum[lane] = v;
    }
    __syncthreads();
    int base = inc - s + ((wid > 0) ? wsum[wid-1] : 0);
    #pragma unroll
    for (int k = 0; k < 5; k++) {
        int idx = t*5 + k;
        if (idx < NCELL && vals[k]) g_aliveList[base++] = idx;
    }
    if (t == 1023) g_nAlive = inc + ((wid > 0) ? wsum[wid-1] : 0) - 0;
    /* note: inc for t=1023 is total inclusive sum of last warp; total = wsum[31] */
    if (t == 0) { /* placeholder */ }
    __syncthreads();
    if (t == 0) g_nAlive = wsum[31];
}

/* ---------------- K4: out partials over compacted alive cells ------------- */
__global__ void __launch_bounds__(192, 2) k_out(const float* __restrict__ E) {
    int cg = blockIdx.x >> 1;
    int hg = blockIdx.x & 1;
    int t = threadIdx.x;
    int d4 = t * 4;
    float4 acc[HH];
    #pragma unroll
    for (int h = 0; h < HH; h++) { acc[h].x=0.f; acc[h].y=0.f; acc[h].z=0.f; acc[h].w=0.f; }

    int na = g_nAlive;
    for (int i = cg; i < na; i += K4_CG) {
        int c = g_aliveList[i];
        float4 a = *reinterpret_cast<const float4*>(g_A + c*DD + d4);
        const float4* base = reinterpret_cast<const float4*>(E + c*(CHH*DD) + hg*HH*DD + d4);
        #pragma unroll
        for (int h = 0; h < HH; h++) {
            float4 e = __ldcs(base + h*(DD/4));
            acc[h].x += a.x * e.x;
            acc[h].y += a.y * e.y;
            acc[h].z += a.z * e.z;
            acc[h].w += a.w * e.w;
        }
    }
    float* pb = g_part + blockIdx.x * (HH*DD);
    #pragma unroll
    for (int h = 0; h < HH; h++)
        *reinterpret_cast<float4*>(pb + h*DD + d4) = acc[h];
}

/* ---------------- K5: reduce partials -> d_out ---------------------------- */
__global__ void k_reduce(float* __restrict__ out) {
    int idx = blockIdx.x * blockDim.x + threadIdx.x;   /* 5760 threads */
    if (idx >= (NHH * DD) / 4) return;
    int h  = idx / (DD/4);
    int d4 = (idx - h*(DD/4)) * 4;
    int g  = h / HH;
    int hh = h - g*HH;
    float ax=0.f, ay=0.f, az=0.f, aw=0.f;
    #pragma unroll 4
    for (int cg = 0; cg < K4_CG; cg++) {
        const float4 v = *reinterpret_cast<const float4*>(
            g_part + (cg*2 + g) * (HH*DD) + hh*DD + d4);
        ax += v.x; ay += v.y; az += v.z; aw += v.w;
    }
    float4 o; o.x=ax; o.y=ay; o.z=az; o.w=aw;
    *reinterpret_cast<float4*>(out + h*DD + d4) = o;
}

/* ---------------- launcher ------------------------------------------------ */
extern "C" void kernel_launch(void* const* d_in, const int* in_sizes, int n_in,
                              void* d_out, int out_size) {
    const float* samples = (const float*)d_in[0];
    const float* lastp   = (const float*)d_in[1];
    const float* E       = (const float*)d_in[2];
    for (int i = 0; i < n_in; i++) {
        if (in_sizes[i] == NS * 3)            samples = (const float*)d_in[i];
        else if (in_sizes[i] == 3)            lastp   = (const float*)d_in[i];
        else if (in_sizes[i] > 1000000)       E       = (const float*)d_in[i];
    }

    k_init          <<<(NCELL + 255)/256, 256>>>();
    k_prep          <<<(NS + 255)/256, 256>>>(samples, lastp);
    k_build         <<<1, 1024>>>();
    k_density_front <<<FRONT, 192>>>(E);
    k_wgt_front     <<<4, 192>>>();
    k_density_rest  <<<NS - FRONT, 192>>>(E);
    k_wgt_rest      <<<4, 192>>>();
    k_A             <<<NCELL, 192>>>();
    k_compact       <<<1, 1024>>>();
    k_out           <<<K4_GRID, 192>>>(E);
    k_reduce        <<<30, 192>>>((float*)d_out);
    (void)out_size;
}